// round 16
// baseline (speedup 1.0000x reference)
#include <cuda_runtime.h>
#include <cuda_bf16.h>
#include <math.h>
#include <stdint.h>

#define BSZ   8
#define TSEQ  2048
#define CDIM  1024
#define HD    64

typedef unsigned int u32;

// W in mma B-fragment layout: [ntile(24)][stage(32)][lane(32)] uint4
__device__ __align__(16) uint4 g_wfh[24 * 32 * 32];
__device__ __align__(16) uint4 g_wfl[24 * 32 * 32];

// split-bf16 attention operands (written by qkv kernel)
__device__ __align__(16) __nv_bfloat16 g_qh[BSZ * TSEQ * HD];  // pre-scaled 0.125
__device__ __align__(16) __nv_bfloat16 g_ql[BSZ * TSEQ * HD];
__device__ __align__(16) __nv_bfloat16 g_kh[BSZ * TSEQ * HD];
__device__ __align__(16) __nv_bfloat16 g_kl[BSZ * TSEQ * HD];
__device__ __align__(16) __nv_bfloat16 g_vth[BSZ * HD * TSEQ]; // [b][d][t]
__device__ __align__(16) __nv_bfloat16 g_vtl[BSZ * HD * TSEQ];

__device__ __forceinline__ u32 bf2(float lo, float hi) {
    u32 r; asm("cvt.rn.bf16x2.f32 %0, %1, %2;" : "=r"(r) : "f"(hi), "f"(lo));
    return r;
}
__device__ __forceinline__ void split2(float a, float b, u32& hi, u32& lo) {
    hi = bf2(a, b);
    float ha = __uint_as_float(hi << 16);
    float hb = __uint_as_float(hi & 0xffff0000u);
    lo = bf2(a - ha, b - hb);
}
__device__ __forceinline__ void mma16816(float c[4], const u32 a[4], const u32 b[2]) {
    asm volatile(
        "mma.sync.aligned.m16n8k16.row.col.f32.bf16.bf16.f32 "
        "{%0,%1,%2,%3}, {%4,%5,%6,%7}, {%8,%9}, {%0,%1,%2,%3};"
        : "+f"(c[0]), "+f"(c[1]), "+f"(c[2]), "+f"(c[3])
        : "r"(a[0]), "r"(a[1]), "r"(a[2]), "r"(a[3]), "r"(b[0]), "r"(b[1]));
}
__device__ __forceinline__ void ldm_x4(u32* r, u32 addr) {
    asm volatile("ldmatrix.sync.aligned.m8n8.x4.shared.b16 {%0,%1,%2,%3}, [%4];"
                 : "=r"(r[0]), "=r"(r[1]), "=r"(r[2]), "=r"(r[3]) : "r"(addr));
}
__device__ __forceinline__ u32 smem_u32(const void* p) {
    u32 a;
    asm("{ .reg .u64 t; cvta.to.shared.u64 t, %1; cvt.u32.u64 %0, t; }"
        : "=r"(a) : "l"(p));
    return a;
}

// ---------------------------------------------------------------------------
// Kernel 0: pack W into split-bf16 mma B-fragments.
// idx = (ntile*32 + st)*32 + lane;  n = ntile*8 + (lane>>2);
// frag reg m = pack(W[k][n], W[k+1][n]) with k = st*32 + m*8 + 2*(lane&3).
// ---------------------------------------------------------------------------
__global__ __launch_bounds__(256) void wprep_kernel(const float* __restrict__ W)
{
    int idx = blockIdx.x * 256 + threadIdx.x;   // 0..24575
    int lane  = idx & 31;
    int st    = (idx >> 5) & 31;
    int ntile = idx >> 10;
    int n  = ntile * 8 + (lane >> 2);
    int kb = st * 32 + 2 * (lane & 3);
    uint4 h, l;
#pragma unroll
    for (int m = 0; m < 4; m++) {
        int k = kb + m * 8;
        float w0 = W[(size_t)k * 192 + n];
        float w1 = W[(size_t)(k + 1) * 192 + n];
        u32 hm, lm;
        split2(w0, w1, hm, lm);
        (&h.x)[m] = hm;
        (&l.x)[m] = lm;
    }
    g_wfh[idx] = h;
    g_wfl[idx] = l;
}

// ---------------------------------------------------------------------------
// Kernel 1: QKV projection.  BM=128, BN=192, BK=32, grid 128, 384 thr
// (12 warps = 4M x 3N).  W operands come straight from gmem as prepacked
// fragments (1 LDG.128 each, L1/L2-resident, identical across CTAs) — no W
// cp.async, no W smem, no W ldmatrix.  x double-buffered in 40 KB static smem.
// ---------------------------------------------------------------------------
#define QKV_XHI 0
#define QKV_XLO 2560
#define QKV_BUF_WORDS 5120   // one buffer: XHI + XLO

__global__ __launch_bounds__(384) void qkv_mma_kernel(
    const float* __restrict__ x, const float* __restrict__ bias)
{
    __shared__ u32 qsm[2 * QKV_BUF_WORDS];   // 40 KB
    const u32 sb = smem_u32(qsm);

    const int tid  = threadIdx.x;
    const int wid  = tid >> 5, lane = tid & 31;
    const int g    = lane >> 2, t = lane & 3;
    const int bm   = blockIdx.x;
    const int wm0  = (wid & 3) * 32;
    const int wn0  = (wid >> 2) * 64;      // 0 / 64 / 128
    const int nt0  = (wid >> 2) * 8;       // base ntile

    const int arow = lane & 7;
    const int tsel = lane >> 3;

    // x loader (threads 0..255): row = tid>>1, 16 floats at (tid&1)*16
    const int xrow = tid >> 1;
    const float* xsrc = x + ((size_t)(bm * 128 + (xrow & 127))) * CDIM + (tid & 1) * 16;
    const u32 xw0 = (xrow & 127) * 20 + (tid & 1) * 8;
    const bool xldr = (tid < 256);

    float c[2][8][4];
#pragma unroll
    for (int i = 0; i < 2; i++)
#pragma unroll
        for (int j = 0; j < 8; j++)
#pragma unroll
            for (int q = 0; q < 4; q++) c[i][j][q] = 0.f;

    float4 xv[4];
    // ---- prologue: stage 0 x tile into buffer 0 ----
    if (xldr) {
#pragma unroll
        for (int q = 0; q < 4; q++)
            xv[q] = *reinterpret_cast<const float4*>(xsrc + q * 4);
        u32* dh = qsm + QKV_XHI + xw0;
        u32* dl = qsm + QKV_XLO + xw0;
#pragma unroll
        for (int q = 0; q < 4; q++) {
            u32 h0, l0, h1, l1;
            split2(xv[q].x, xv[q].y, h0, l0);
            split2(xv[q].z, xv[q].w, h1, l1);
            dh[q * 2] = h0; dh[q * 2 + 1] = h1;
            dl[q * 2] = l0; dl[q * 2 + 1] = l1;
        }
    }
    __syncthreads();

    for (int st = 0; st < 32; st++) {
        const u32 bufoff = (u32)(st & 1) * QKV_BUF_WORDS;

        // prefetch next x tile into registers (overlaps MMA)
        if (st < 31 && xldr) {
            const int k1 = (st + 1) * 32;
#pragma unroll
            for (int q = 0; q < 4; q++)
                xv[q] = *reinterpret_cast<const float4*>(xsrc + k1 + q * 4);
        }

        // ---- A fragments from smem (ldmatrix) ----
        const u32 base = sb + bufoff * 4;
        u32 Ah[2][2][4], Al[2][2][4];
#pragma unroll
        for (int i = 0; i < 2; i++)
#pragma unroll
            for (int ks = 0; ks < 2; ks++) {
                const u32 aoff = (u32)((wm0 + i * 16 + ((tsel & 1) << 3) + arow) * 20
                                       + ks * 8 + ((tsel >> 1) << 2)) * 4;
                ldm_x4(Ah[i][ks], base + QKV_XHI * 4 + aoff);
                ldm_x4(Al[i][ks], base + QKV_XLO * 4 + aoff);
            }

        // ---- W fragments straight from gmem, pipelined over j ----
        const int wb = nt0 * 1024 + st * 32 + lane;
        uint4 bh = g_wfh[wb], bl = g_wfl[wb];
#pragma unroll
        for (int j = 0; j < 8; j++) {
            uint4 nbh, nbl;
            if (j < 7) {
                nbh = g_wfh[wb + (j + 1) * 1024];
                nbl = g_wfl[wb + (j + 1) * 1024];
            }
            u32 bh0[2] = { bh.x, bh.y }, bh1[2] = { bh.z, bh.w };
            u32 bl0[2] = { bl.x, bl.y }, bl1[2] = { bl.z, bl.w };
#pragma unroll
            for (int i = 0; i < 2; i++) {
                mma16816(c[i][j], Ah[i][0], bh0);
                mma16816(c[i][j], Al[i][0], bh0);
                mma16816(c[i][j], Ah[i][0], bl0);
                mma16816(c[i][j], Ah[i][1], bh1);
                mma16816(c[i][j], Al[i][1], bh1);
                mma16816(c[i][j], Ah[i][1], bl1);
            }
            bh = nbh; bl = nbl;
        }

        // ---- store next x tile into the other buffer ----
        if (st < 31 && xldr) {
            const u32 nxtoff = bufoff ^ QKV_BUF_WORDS;
            u32* dh = qsm + nxtoff + QKV_XHI + xw0;
            u32* dl = qsm + nxtoff + QKV_XLO + xw0;
#pragma unroll
            for (int q = 0; q < 4; q++) {
                u32 h0, l0, h1, l1;
                split2(xv[q].x, xv[q].y, h0, l0);
                split2(xv[q].z, xv[q].w, h1, l1);
                dh[q * 2] = h0; dh[q * 2 + 1] = h1;
                dl[q * 2] = l0; dl[q * 2 + 1] = l1;
            }
        }
        __syncthreads();
    }

    // ---- epilogue: +bias, split to bf16 hi/lo, store.  Warp-uniform blk. ----
    const int blk = wn0 >> 6;            // 0=k, 1=q, 2=v (uniform per warp)
#pragma unroll
    for (int i = 0; i < 2; i++) {
        const int row0 = bm * 128 + wm0 + i * 16 + g;
#pragma unroll
        for (int j = 0; j < 8; j++) {
            const int col = j * 8 + 2 * t;           // 0..62 within block
            const float bz0 = bias[wn0 + col], bz1 = bias[wn0 + col + 1];
            float v00 = c[i][j][0] + bz0, v01 = c[i][j][1] + bz1;
            float v10 = c[i][j][2] + bz0, v11 = c[i][j][3] + bz1;
            if (blk == 2) {
                const int bidx = row0 >> 11;
                const int tt   = row0 & 2047;
                size_t p0 = (size_t)(bidx * 64 + col) * 2048 + tt;
                size_t p1 = p0 + 2048;
                __nv_bfloat16 h;
                h = __float2bfloat16(v00); g_vth[p0] = h;
                g_vtl[p0] = __float2bfloat16(v00 - __bfloat162float(h));
                h = __float2bfloat16(v01); g_vth[p1] = h;
                g_vtl[p1] = __float2bfloat16(v01 - __bfloat162float(h));
                h = __float2bfloat16(v10); g_vth[p0 + 8] = h;
                g_vtl[p0 + 8] = __float2bfloat16(v10 - __bfloat162float(h));
                h = __float2bfloat16(v11); g_vth[p1 + 8] = h;
                g_vtl[p1 + 8] = __float2bfloat16(v11 - __bfloat162float(h));
            } else {
                __nv_bfloat16* dh = blk ? g_qh : g_kh;
                __nv_bfloat16* dl = blk ? g_ql : g_kl;
                const float sc = blk ? 0.125f : 1.0f;
                v00 *= sc; v01 *= sc; v10 *= sc; v11 *= sc;
                u32 h0, l0, h1, l1;
                split2(v00, v01, h0, l0);
                split2(v10, v11, h1, l1);
                *reinterpret_cast<u32*>(dh + (size_t)row0 * HD + col) = h0;
                *reinterpret_cast<u32*>(dl + (size_t)row0 * HD + col) = l0;
                *reinterpret_cast<u32*>(dh + (size_t)(row0 + 8) * HD + col) = h1;
                *reinterpret_cast<u32*>(dl + (size_t)(row0 + 8) * HD + col) = l1;
            }
        }
    }
}

// ---------------------------------------------------------------------------
// Kernel 2: causal flash attention, HMMA + ldmatrix, 3-way split-K groups.
// 384 thr = 3 groups of 4 warps; group gp handles kt == gp (mod 3).
// Grid (16, 8); pairing (qt, 31-qt).  [R11/R15 version — best measured]
// ---------------------------------------------------------------------------
#define KTW   36
#define PLANE (64 * KTW)
#define BUF_WORDS (4 * PLANE)
#define GRP_WORDS (2 * BUF_WORDS)
#define NGRP 3
#define MO_STR 66
#define ATTN_SMEM (NGRP * GRP_WORDS * 4) // 221184 B

__device__ __forceinline__ void barg(int id) {
    asm volatile("bar.sync %0, 128;" :: "r"(id) : "memory");
}

__device__ __forceinline__ void cp_tile(u32 base_bytes, int t0, int ltid,
    const __nv_bfloat16* kh_g, const __nv_bfloat16* kl_g,
    const __nv_bfloat16* vh_g, const __nv_bfloat16* vl_g)
{
#pragma unroll
    for (int i = 0; i < 4; i++) {
        int id = i * 128 + ltid;
        int row = id >> 3, ch = id & 7;
        u32 soff = (u32)(row * KTW + ch * 4) * 4;
        const void* s1 = kh_g + (size_t)(t0 + row) * HD + ch * 8;
        const void* s2 = kl_g + (size_t)(t0 + row) * HD + ch * 8;
        const void* s3 = vh_g + (size_t)row * TSEQ + t0 + ch * 8;
        const void* s4 = vl_g + (size_t)row * TSEQ + t0 + ch * 8;
        asm volatile("cp.async.ca.shared.global [%0], [%1], 16;"
                     :: "r"(base_bytes + 0 * PLANE * 4 + soff), "l"(s1) : "memory");
        asm volatile("cp.async.ca.shared.global [%0], [%1], 16;"
                     :: "r"(base_bytes + 1 * PLANE * 4 + soff), "l"(s2) : "memory");
        asm volatile("cp.async.ca.shared.global [%0], [%1], 16;"
                     :: "r"(base_bytes + 2 * PLANE * 4 + soff), "l"(s3) : "memory");
        asm volatile("cp.async.ca.shared.global [%0], [%1], 16;"
                     :: "r"(base_bytes + 3 * PLANE * 4 + soff), "l"(s4) : "memory");
    }
    asm volatile("cp.async.commit_group;" ::: "memory");
}

__global__ __launch_bounds__(384, 1) void attn_hmma_kernel(float* __restrict__ out)
{
    extern __shared__ u32 smem_dyn[];
    const u32 sbase = smem_u32(smem_dyn);

    const int tid = threadIdx.x;
    const int w = tid >> 5, lane = tid & 31;
    const int gp = w >> 2;
    const int wg = w & 3;
    const int g = lane >> 2, t = lane & 3;
    const int ltid = tid & 127;
    const int brow = lane & 7, bsel = lane >> 3;
    const int bb = blockIdx.y, bx = blockIdx.x;

    const __nv_bfloat16* qh_g = g_qh + (size_t)bb * TSEQ * HD;
    const __nv_bfloat16* ql_g = g_ql + (size_t)bb * TSEQ * HD;
    const __nv_bfloat16* kh_g = g_kh + (size_t)bb * TSEQ * HD;
    const __nv_bfloat16* kl_g = g_kl + (size_t)bb * TSEQ * HD;
    const __nv_bfloat16* vh_g = g_vth + (size_t)bb * HD * TSEQ;
    const __nv_bfloat16* vl_g = g_vtl + (size_t)bb * HD * TSEQ;

    const u32 gbase = sbase + (u32)gp * GRP_WORDS * 4;
    float* mo  = (float*)smem_dyn;                 // [2][64][MO_STR]
    float* mmv = mo + 2 * 64 * MO_STR;             // [2][64]
    float* mlv = mmv + 2 * 64;                     // [2][64]

    for (int half = 0; half < 2; half++) {
        const int qt = half ? 31 - bx : bx;
        const int qrow0 = qt * 64;
        const int r0 = wg * 16 + g;

        u32 qh[4][4], ql[4][4];
#pragma unroll
        for (int kk = 0; kk < 4; kk++) {
            const size_t b0 = (size_t)(qrow0 + r0) * HD + kk * 16 + 2 * t;
            const size_t b1 = b0 + 8 * HD;
            qh[kk][0] = *(const u32*)(qh_g + b0);
            qh[kk][1] = *(const u32*)(qh_g + b1);
            qh[kk][2] = *(const u32*)(qh_g + b0 + 8);
            qh[kk][3] = *(const u32*)(qh_g + b1 + 8);
            ql[kk][0] = *(const u32*)(ql_g + b0);
            ql[kk][1] = *(const u32*)(ql_g + b1);
            ql[kk][2] = *(const u32*)(ql_g + b0 + 8);
            ql[kk][3] = *(const u32*)(ql_g + b1 + 8);
        }

        float o[8][4];
#pragma unroll
        for (int nt = 0; nt < 8; nt++)
#pragma unroll
            for (int q = 0; q < 4; q++) o[nt][q] = 0.f;
        float m0 = -1e30f, m1 = -1e30f, l0 = 0.f, l1 = 0.f;

        const int n_t = (qt >= gp) ? ((qt - gp) / 3) + 1 : 0;
        if (n_t > 0) cp_tile(gbase, gp * 64, ltid, kh_g, kl_g, vh_g, vl_g);

        for (int i = 0; i < n_t; i++) {
            const int kt = gp + 3 * i;
            const int t0 = kt * 64;
            if (i + 1 < n_t) {
                cp_tile(gbase + (u32)((i + 1) & 1) * BUF_WORDS * 4,
                        (gp + 3 * (i + 1)) * 64, ltid, kh_g, kl_g, vh_g, vl_g);
                asm volatile("cp.async.wait_group 1;" ::: "memory");
            } else {
                asm volatile("cp.async.wait_group 0;" ::: "memory");
            }
            barg(1 + gp);

            const u32 bufb = gbase + (u32)(i & 1) * BUF_WORDS * 4;

            // ---- GEMM1: S = Q @ K^T ----
            float s[8][4];
#pragma unroll
            for (int nt = 0; nt < 8; nt++)
#pragma unroll
                for (int q = 0; q < 4; q++) s[nt][q] = 0.f;
#pragma unroll
            for (int nt = 0; nt < 8; nt++) {
                const u32 bb0 = bufb + (u32)((nt * 8 + brow) * KTW + bsel * 4) * 4;
                u32 bh[4], bl[4];
                ldm_x4(bh, bb0);
                ldm_x4(bl, bb0 + PLANE * 4);
                mma16816(s[nt], qh[0], bh + 0);
                mma16816(s[nt], ql[0], bh + 0);
                mma16816(s[nt], qh[0], bl + 0);
                mma16816(s[nt], qh[1], bh + 2);
                mma16816(s[nt], ql[1], bh + 2);
                mma16816(s[nt], qh[1], bl + 2);
                ldm_x4(bh, bb0 + 64);
                ldm_x4(bl, bb0 + PLANE * 4 + 64);
                mma16816(s[nt], qh[2], bh + 0);
                mma16816(s[nt], ql[2], bh + 0);
                mma16816(s[nt], qh[2], bl + 0);
                mma16816(s[nt], qh[3], bh + 2);
                mma16816(s[nt], ql[3], bh + 2);
                mma16816(s[nt], qh[3], bl + 2);
            }

            if (kt == qt) {
                const int rg = qrow0 + r0;
#pragma unroll
                for (int nt = 0; nt < 8; nt++) {
                    const int col = t0 + nt * 8 + 2 * t;
                    if (col     > rg)     s[nt][0] = -1e30f;
                    if (col + 1 > rg)     s[nt][1] = -1e30f;
                    if (col     > rg + 8) s[nt][2] = -1e30f;
                    if (col + 1 > rg + 8) s[nt][3] = -1e30f;
                }
            }

            // ---- streaming softmax ----
            float mx0 = -1e30f, mx1 = -1e30f;
#pragma unroll
            for (int nt = 0; nt < 8; nt++) {
                mx0 = fmaxf(mx0, fmaxf(s[nt][0], s[nt][1]));
                mx1 = fmaxf(mx1, fmaxf(s[nt][2], s[nt][3]));
            }
            mx0 = fmaxf(mx0, __shfl_xor_sync(0xffffffffu, mx0, 1));
            mx0 = fmaxf(mx0, __shfl_xor_sync(0xffffffffu, mx0, 2));
            mx1 = fmaxf(mx1, __shfl_xor_sync(0xffffffffu, mx1, 1));
            mx1 = fmaxf(mx1, __shfl_xor_sync(0xffffffffu, mx1, 2));
            const float mn0 = fmaxf(m0, mx0), mn1 = fmaxf(m1, mx1);
            const float c0r = __expf(m0 - mn0), c1r = __expf(m1 - mn1);
            m0 = mn0; m1 = mn1;

            float s0 = 0.f, s1 = 0.f;
            u32 ph[4][4], pl[4][4];
#pragma unroll
            for (int q2 = 0; q2 < 4; q2++) {
                float p00 = __expf(s[2*q2][0]   - mn0), p01 = __expf(s[2*q2][1]   - mn0);
                float p02 = __expf(s[2*q2][2]   - mn1), p03 = __expf(s[2*q2][3]   - mn1);
                float p10 = __expf(s[2*q2+1][0] - mn0), p11 = __expf(s[2*q2+1][1] - mn0);
                float p12 = __expf(s[2*q2+1][2] - mn1), p13 = __expf(s[2*q2+1][3] - mn1);
                s0 += (p00 + p01) + (p10 + p11);
                s1 += (p02 + p03) + (p12 + p13);
                split2(p00, p01, ph[q2][0], pl[q2][0]);
                split2(p02, p03, ph[q2][1], pl[q2][1]);
                split2(p10, p11, ph[q2][2], pl[q2][2]);
                split2(p12, p13, ph[q2][3], pl[q2][3]);
            }
            s0 += __shfl_xor_sync(0xffffffffu, s0, 1);
            s0 += __shfl_xor_sync(0xffffffffu, s0, 2);
            s1 += __shfl_xor_sync(0xffffffffu, s1, 1);
            s1 += __shfl_xor_sync(0xffffffffu, s1, 2);
            l0 = l0 * c0r + s0;
            l1 = l1 * c1r + s1;

#pragma unroll
            for (int nt = 0; nt < 8; nt++) {
                o[nt][0] *= c0r; o[nt][1] *= c0r;
                o[nt][2] *= c1r; o[nt][3] *= c1r;
            }

            // ---- GEMM2: O += P @ V ----
#pragma unroll
            for (int nt = 0; nt < 8; nt++) {
                const u32 vb0 = bufb + 2 * PLANE * 4
                              + (u32)((nt * 8 + brow) * KTW + bsel * 4) * 4;
                u32 bh[4], bl[4];
                ldm_x4(bh, vb0);
                ldm_x4(bl, vb0 + PLANE * 4);
                mma16816(o[nt], ph[0], bh + 0);
                mma16816(o[nt], pl[0], bh + 0);
                mma16816(o[nt], ph[0], bl + 0);
                mma16816(o[nt], ph[1], bh + 2);
                mma16816(o[nt], pl[1], bh + 2);
                mma16816(o[nt], ph[1], bl + 2);
                ldm_x4(bh, vb0 + 64);
                ldm_x4(bl, vb0 + PLANE * 4 + 64);
                mma16816(o[nt], ph[2], bh + 0);
                mma16816(o[nt], pl[2], bh + 0);
                mma16816(o[nt], ph[2], bl + 0);
                mma16816(o[nt], ph[3], bh + 2);
                mma16816(o[nt], pl[3], bh + 2);
                mma16816(o[nt], ph[3], bl + 2);
            }
            barg(1 + gp);
        }

        // ---- 3-way merge (staging reuses group-0 buffers) ----
        __syncthreads();
        if (gp >= 1) {
            const int gi = gp - 1;
            float* mog = mo + gi * 64 * MO_STR;
            const int ra = r0, rb = r0 + 8;
#pragma unroll
            for (int nt = 0; nt < 8; nt++) {
                const int cc = nt * 8 + 2 * t;
                mog[ra * MO_STR + cc]     = o[nt][0];
                mog[ra * MO_STR + cc + 1] = o[nt][1];
                mog[rb * MO_STR + cc]     = o[nt][2];
                mog[rb * MO_STR + cc + 1] = o[nt][3];
            }
            if (t == 0) {
                mmv[gi * 64 + ra] = m0; mlv[gi * 64 + ra] = l0;
                mmv[gi * 64 + rb] = m1; mlv[gi * 64 + rb] = l1;
            }
        }
        __syncthreads();
        if (gp == 0) {
            const int ra = r0, rb = r0 + 8;
            const float m1a = mmv[ra],      l1a = mlv[ra];
            const float m2a = mmv[64 + ra], l2a = mlv[64 + ra];
            const float m1b = mmv[rb],      l1b = mlv[rb];
            const float m2b = mmv[64 + rb], l2b = mlv[64 + rb];
            const float msA = fmaxf(m0, fmaxf(m1a, m2a));
            const float msB = fmaxf(m1, fmaxf(m1b, m2b));
            const float f0A = __expf(m0 - msA), f1A = __expf(m1a - msA), f2A = __expf(m2a - msA);
            const float f0B = __expf(m1 - msB), f1B = __expf(m1b - msB), f2B = __expf(m2b - msB);
            const float invA = 1.f / (l0 * f0A + l1a * f1A + l2a * f2A);
            const float invB = 1.f / (l1 * f0B + l1b * f1B + l2b * f2B);
            const float* mo1 = mo;
            const float* mo2 = mo + 64 * MO_STR;
            float* orow0 = out + ((size_t)bb * TSEQ + qrow0 + ra) * HD;
            float* orow1 = out + ((size_t)bb * TSEQ + qrow0 + rb) * HD;
#pragma unroll
            for (int nt = 0; nt < 8; nt++) {
                const int cc = nt * 8 + 2 * t;
                float2 oa, ob;
                oa.x = (o[nt][0] * f0A + mo1[ra * MO_STR + cc]     * f1A
                                       + mo2[ra * MO_STR + cc]     * f2A) * invA;
                oa.y = (o[nt][1] * f0A + mo1[ra * MO_STR + cc + 1] * f1A
                                       + mo2[ra * MO_STR + cc + 1] * f2A) * invA;
                ob.x = (o[nt][2] * f0B + mo1[rb * MO_STR + cc]     * f1B
                                       + mo2[rb * MO_STR + cc]     * f2B) * invB;
                ob.y = (o[nt][3] * f0B + mo1[rb * MO_STR + cc + 1] * f1B
                                       + mo2[rb * MO_STR + cc + 1] * f2B) * invB;
                *reinterpret_cast<float2*>(orow0 + cc) = oa;
                *reinterpret_cast<float2*>(orow1 + cc) = ob;
            }
        }
        __syncthreads();
    }
}

// ---------------------------------------------------------------------------
extern "C" void kernel_launch(void* const* d_in, const int* in_sizes, int n_in,
                              void* d_out, int out_size)
{
    const float* x = (const float*)d_in[0];
    const float* W = (const float*)d_in[1];
    const float* b = (const float*)d_in[2];
    float* out = (float*)d_out;

    (void)in_sizes; (void)n_in; (void)out_size;

    static int attr_set = 0;
    if (!attr_set) {
        cudaFuncSetAttribute(attn_hmma_kernel,
                             cudaFuncAttributeMaxDynamicSharedMemorySize, ATTN_SMEM);
        attr_set = 1;
    }

    wprep_kernel<<<96, 256>>>(W);
    qkv_mma_kernel<<<128, 384>>>(x, b);

    dim3 g2(16, BSZ);
    attn_hmma_kernel<<<g2, 384, ATTN_SMEM>>>(out);
}

// round 17
// speedup vs baseline: 1.1723x; 1.1723x over previous
#include <cuda_runtime.h>
#include <cuda_bf16.h>
#include <cuda_fp16.h>
#include <math.h>
#include <stdint.h>

#define BSZ   8
#define TSEQ  2048
#define CDIM  1024
#define HD    64

typedef unsigned int u32;

// split-bf16 W transposed ([192][1024])
__device__ __align__(16) __nv_bfloat16 g_wt_hi[192 * CDIM];
__device__ __align__(16) __nv_bfloat16 g_wt_lo[192 * CDIM];

// attention operands (written by qkv kernel)
__device__ __align__(16) __nv_bfloat16 g_qh[BSZ * TSEQ * HD];  // pre-scaled 0.125
__device__ __align__(16) __nv_bfloat16 g_ql[BSZ * TSEQ * HD];
__device__ __align__(16) __nv_bfloat16 g_kh[BSZ * TSEQ * HD];
__device__ __align__(16) __nv_bfloat16 g_kl[BSZ * TSEQ * HD];
__device__ __align__(16) __half       g_vth[BSZ * HD * TSEQ]; // [b][d][t], single fp16

__device__ __forceinline__ u32 bf2(float lo, float hi) {
    u32 r; asm("cvt.rn.bf16x2.f32 %0, %1, %2;" : "=r"(r) : "f"(hi), "f"(lo));
    return r;
}
__device__ __forceinline__ u32 h2pk(float lo, float hi) {
    u32 r; asm("cvt.rn.f16x2.f32 %0, %1, %2;" : "=r"(r) : "f"(hi), "f"(lo));
    return r;
}
__device__ __forceinline__ void split2(float a, float b, u32& hi, u32& lo) {
    hi = bf2(a, b);
    float ha = __uint_as_float(hi << 16);
    float hb = __uint_as_float(hi & 0xffff0000u);
    lo = bf2(a - ha, b - hb);
}
__device__ __forceinline__ void mma16816(float c[4], const u32 a[4], const u32 b[2]) {
    asm volatile(
        "mma.sync.aligned.m16n8k16.row.col.f32.bf16.bf16.f32 "
        "{%0,%1,%2,%3}, {%4,%5,%6,%7}, {%8,%9}, {%0,%1,%2,%3};"
        : "+f"(c[0]), "+f"(c[1]), "+f"(c[2]), "+f"(c[3])
        : "r"(a[0]), "r"(a[1]), "r"(a[2]), "r"(a[3]), "r"(b[0]), "r"(b[1]));
}
__device__ __forceinline__ void mma16816h(float c[4], const u32 a[4], const u32 b[2]) {
    asm volatile(
        "mma.sync.aligned.m16n8k16.row.col.f32.f16.f16.f32 "
        "{%0,%1,%2,%3}, {%4,%5,%6,%7}, {%8,%9}, {%0,%1,%2,%3};"
        : "+f"(c[0]), "+f"(c[1]), "+f"(c[2]), "+f"(c[3])
        : "r"(a[0]), "r"(a[1]), "r"(a[2]), "r"(a[3]), "r"(b[0]), "r"(b[1]));
}
__device__ __forceinline__ void ldm_x4(u32* r, u32 addr) {
    asm volatile("ldmatrix.sync.aligned.m8n8.x4.shared.b16 {%0,%1,%2,%3}, [%4];"
                 : "=r"(r[0]), "=r"(r[1]), "=r"(r[2]), "=r"(r[3]) : "r"(addr));
}
__device__ __forceinline__ u32 smem_u32(const void* p) {
    u32 a;
    asm("{ .reg .u64 t; cvta.to.shared.u64 t, %1; cvt.u32.u64 %0, t; }"
        : "=r"(a) : "l"(p));
    return a;
}

// ---------------------------------------------------------------------------
// Kernel 0: prep split-bf16 transposed weights (tiny).
// ---------------------------------------------------------------------------
__global__ __launch_bounds__(256) void wprep_kernel(const float* __restrict__ W)
{
    int idx = blockIdx.x * 256 + threadIdx.x;
    if (idx >= 192 * CDIM) return;
    int n = idx >> 10, k = idx & 1023;
    float w = W[(size_t)k * 192 + n];
    __nv_bfloat16 hi = __float2bfloat16(w);
    g_wt_hi[(size_t)n * CDIM + k] = hi;
    g_wt_lo[(size_t)n * CDIM + k] = __float2bfloat16(w - __bfloat162float(hi));
}

// ---------------------------------------------------------------------------
// Kernel 1: QKV projection (R15 version, best measured).  BM=128, BN=192,
// BK=32, grid 128, 384 thr = 12 warps (4M x 3N).  V stored as single fp16.
// ---------------------------------------------------------------------------
#define QKV_XHI 0
#define QKV_XLO 2560
#define QKV_WHI 5120
#define QKV_WLO 8960
#define QKV_BUF_WORDS 12800
#define QKV_SMEM_BYTES (2 * QKV_BUF_WORDS * 4)   // 102400

__device__ __forceinline__ void qkv_cpW(u32 sb, u32 bufoff, int k0, int tid)
{
#pragma unroll
    for (int i = 0; i < 2; i++) {
        int idx = i * 384 + tid;              // 0..767
        int n = idx >> 2, ch = idx & 3;
        u32 dhi = sb + (bufoff + QKV_WHI + n * 20 + ch * 4) * 4;
        u32 dlo = sb + (bufoff + QKV_WLO + n * 20 + ch * 4) * 4;
        const void* shi = g_wt_hi + (size_t)n * CDIM + k0 + ch * 8;
        const void* slo = g_wt_lo + (size_t)n * CDIM + k0 + ch * 8;
        asm volatile("cp.async.ca.shared.global [%0], [%1], 16;"
                     :: "r"(dhi), "l"(shi) : "memory");
        asm volatile("cp.async.ca.shared.global [%0], [%1], 16;"
                     :: "r"(dlo), "l"(slo) : "memory");
    }
    asm volatile("cp.async.commit_group;" ::: "memory");
}

__global__ __launch_bounds__(384) void qkv_mma_kernel(
    const float* __restrict__ x, const float* __restrict__ bias)
{
    extern __shared__ u32 qsm[];
    const u32 sb = smem_u32(qsm);

    const int tid  = threadIdx.x;
    const int wid  = tid >> 5, lane = tid & 31;
    const int g    = lane >> 2, t = lane & 3;
    const int bm   = blockIdx.x;
    const int wm0  = (wid & 3) * 32;
    const int wn0  = (wid >> 2) * 64;     // 0 / 64 / 128

    const int arow = lane & 7;
    const int tsel = lane >> 3;

    const int xrow = tid >> 1;
    const float* xsrc = x + ((size_t)(bm * 128 + (xrow & 127))) * CDIM + (tid & 1) * 16;
    const u32 xw0 = (xrow & 127) * 20 + (tid & 1) * 8;
    const bool xldr = (tid < 256);

    float c[2][8][4];
#pragma unroll
    for (int i = 0; i < 2; i++)
#pragma unroll
        for (int j = 0; j < 8; j++)
#pragma unroll
            for (int q = 0; q < 4; q++) c[i][j][q] = 0.f;

    float4 xv[4];
    if (xldr) {
#pragma unroll
        for (int q = 0; q < 4; q++)
            xv[q] = *reinterpret_cast<const float4*>(xsrc + q * 4);
    }
    qkv_cpW(sb, 0, 0, tid);
    if (xldr) {
        u32* dh = qsm + QKV_XHI + xw0;
        u32* dl = qsm + QKV_XLO + xw0;
#pragma unroll
        for (int q = 0; q < 4; q++) {
            u32 h0, l0, h1, l1;
            split2(xv[q].x, xv[q].y, h0, l0);
            split2(xv[q].z, xv[q].w, h1, l1);
            dh[q * 2] = h0; dh[q * 2 + 1] = h1;
            dl[q * 2] = l0; dl[q * 2 + 1] = l1;
        }
    }
    asm volatile("cp.async.wait_group 0;" ::: "memory");
    __syncthreads();

    for (int st = 0; st < 32; st++) {
        const u32 bufoff = (u32)(st & 1) * QKV_BUF_WORDS;
        const u32 nxtoff = bufoff ^ QKV_BUF_WORDS;

        if (st < 31) {
            const int k1 = (st + 1) * 32;
            if (xldr) {
#pragma unroll
                for (int q = 0; q < 4; q++)
                    xv[q] = *reinterpret_cast<const float4*>(xsrc + k1 + q * 4);
            }
            qkv_cpW(sb, nxtoff, k1, tid);
        }

        const u32 base = sb + bufoff * 4;
        u32 Ah[2][2][4], Al[2][2][4];
#pragma unroll
        for (int i = 0; i < 2; i++)
#pragma unroll
            for (int ks = 0; ks < 2; ks++) {
                const u32 aoff = (u32)((wm0 + i * 16 + ((tsel & 1) << 3) + arow) * 20
                                       + ks * 8 + ((tsel >> 1) << 2)) * 4;
                ldm_x4(Ah[i][ks], base + QKV_XHI * 4 + aoff);
                ldm_x4(Al[i][ks], base + QKV_XLO * 4 + aoff);
            }
#pragma unroll
        for (int j = 0; j < 8; j++) {
            const u32 boff = (u32)((wn0 + j * 8 + arow) * 20 + tsel * 4) * 4;
            u32 bh[4], bl[4];
            ldm_x4(bh, base + QKV_WHI * 4 + boff);
            ldm_x4(bl, base + QKV_WLO * 4 + boff);
#pragma unroll
            for (int ks = 0; ks < 2; ks++)
#pragma unroll
                for (int i = 0; i < 2; i++) {
                    mma16816(c[i][j], Ah[i][ks], bh + ks * 2);
                    mma16816(c[i][j], Al[i][ks], bh + ks * 2);
                    mma16816(c[i][j], Ah[i][ks], bl + ks * 2);
                }
        }

        if (st < 31) {
            if (xldr) {
                u32* dh = qsm + nxtoff + QKV_XHI + xw0;
                u32* dl = qsm + nxtoff + QKV_XLO + xw0;
#pragma unroll
                for (int q = 0; q < 4; q++) {
                    u32 h0, l0, h1, l1;
                    split2(xv[q].x, xv[q].y, h0, l0);
                    split2(xv[q].z, xv[q].w, h1, l1);
                    dh[q * 2] = h0; dh[q * 2 + 1] = h1;
                    dl[q * 2] = l0; dl[q * 2 + 1] = l1;
                }
            }
            asm volatile("cp.async.wait_group 0;" ::: "memory");
        }
        __syncthreads();
    }

    // ---- epilogue: +bias; k/q split-bf16, v single fp16 (transposed) ----
    const int blk = wn0 >> 6;            // 0=k, 1=q, 2=v (uniform per warp)
#pragma unroll
    for (int i = 0; i < 2; i++) {
        const int row0 = bm * 128 + wm0 + i * 16 + g;
#pragma unroll
        for (int j = 0; j < 8; j++) {
            const int col = j * 8 + 2 * t;
            const float bz0 = bias[wn0 + col], bz1 = bias[wn0 + col + 1];
            float v00 = c[i][j][0] + bz0, v01 = c[i][j][1] + bz1;
            float v10 = c[i][j][2] + bz0, v11 = c[i][j][3] + bz1;
            if (blk == 2) {
                const int bidx = row0 >> 11;
                const int tt   = row0 & 2047;
                size_t p0 = (size_t)(bidx * 64 + col) * 2048 + tt;
                size_t p1 = p0 + 2048;
                g_vth[p0]     = __float2half_rn(v00);
                g_vth[p1]     = __float2half_rn(v01);
                g_vth[p0 + 8] = __float2half_rn(v10);
                g_vth[p1 + 8] = __float2half_rn(v11);
            } else {
                __nv_bfloat16* dh = blk ? g_qh : g_kh;
                __nv_bfloat16* dl = blk ? g_ql : g_kl;
                const float sc = blk ? 0.125f : 1.0f;
                v00 *= sc; v01 *= sc; v10 *= sc; v11 *= sc;
                u32 h0, l0, h1, l1;
                split2(v00, v01, h0, l0);
                split2(v10, v11, h1, l1);
                *reinterpret_cast<u32*>(dh + (size_t)row0 * HD + col) = h0;
                *reinterpret_cast<u32*>(dl + (size_t)row0 * HD + col) = l0;
                *reinterpret_cast<u32*>(dh + (size_t)(row0 + 8) * HD + col) = h1;
                *reinterpret_cast<u32*>(dl + (size_t)(row0 + 8) * HD + col) = l1;
            }
        }
    }
}

// ---------------------------------------------------------------------------
// Kernel 2: causal flash attention.  GEMM1 = split-bf16 3-product (precision
// on logits); GEMM2 = single-product fp16 (P fp16 x V fp16) -> 1/3 the mma.
// 3 planes per buffer (kh, kl, vh).  3-way split-K groups, 384 thr.
// ---------------------------------------------------------------------------
#define KTW   36
#define PLANE (64 * KTW)
#define BUF_WORDS (3 * PLANE)
#define GRP_WORDS (2 * BUF_WORDS)
#define NGRP 3
#define MO_STR 66
#define ATTN_SMEM (NGRP * GRP_WORDS * 4) // 165888 B

__device__ __forceinline__ void barg(int id) {
    asm volatile("bar.sync %0, 128;" :: "r"(id) : "memory");
}

__device__ __forceinline__ void cp_tile(u32 base_bytes, int t0, int ltid,
    const __nv_bfloat16* kh_g, const __nv_bfloat16* kl_g, const __half* vh_g)
{
#pragma unroll
    for (int i = 0; i < 4; i++) {
        int id = i * 128 + ltid;
        int row = id >> 3, ch = id & 7;
        u32 soff = (u32)(row * KTW + ch * 4) * 4;
        const void* s1 = kh_g + (size_t)(t0 + row) * HD + ch * 8;
        const void* s2 = kl_g + (size_t)(t0 + row) * HD + ch * 8;
        const void* s3 = vh_g + (size_t)row * TSEQ + t0 + ch * 8;
        asm volatile("cp.async.ca.shared.global [%0], [%1], 16;"
                     :: "r"(base_bytes + 0 * PLANE * 4 + soff), "l"(s1) : "memory");
        asm volatile("cp.async.ca.shared.global [%0], [%1], 16;"
                     :: "r"(base_bytes + 1 * PLANE * 4 + soff), "l"(s2) : "memory");
        asm volatile("cp.async.ca.shared.global [%0], [%1], 16;"
                     :: "r"(base_bytes + 2 * PLANE * 4 + soff), "l"(s3) : "memory");
    }
    asm volatile("cp.async.commit_group;" ::: "memory");
}

__global__ __launch_bounds__(384, 1) void attn_hmma_kernel(float* __restrict__ out)
{
    extern __shared__ u32 smem_dyn[];
    const u32 sbase = smem_u32(smem_dyn);

    const int tid = threadIdx.x;
    const int w = tid >> 5, lane = tid & 31;
    const int gp = w >> 2;
    const int wg = w & 3;
    const int g = lane >> 2, t = lane & 3;
    const int ltid = tid & 127;
    const int brow = lane & 7, bsel = lane >> 3;
    const int bb = blockIdx.y, bx = blockIdx.x;

    const __nv_bfloat16* qh_g = g_qh + (size_t)bb * TSEQ * HD;
    const __nv_bfloat16* ql_g = g_ql + (size_t)bb * TSEQ * HD;
    const __nv_bfloat16* kh_g = g_kh + (size_t)bb * TSEQ * HD;
    const __nv_bfloat16* kl_g = g_kl + (size_t)bb * TSEQ * HD;
    const __half*        vh_g = g_vth + (size_t)bb * HD * TSEQ;

    const u32 gbase = sbase + (u32)gp * GRP_WORDS * 4;
    float* mo  = (float*)smem_dyn;                 // [2][64][MO_STR]
    float* mmv = mo + 2 * 64 * MO_STR;             // [2][64]
    float* mlv = mmv + 2 * 64;                     // [2][64]

    for (int half = 0; half < 2; half++) {
        const int qt = half ? 31 - bx : bx;
        const int qrow0 = qt * 64;
        const int r0 = wg * 16 + g;

        u32 qh[4][4], ql[4][4];
#pragma unroll
        for (int kk = 0; kk < 4; kk++) {
            const size_t b0 = (size_t)(qrow0 + r0) * HD + kk * 16 + 2 * t;
            const size_t b1 = b0 + 8 * HD;
            qh[kk][0] = *(const u32*)(qh_g + b0);
            qh[kk][1] = *(const u32*)(qh_g + b1);
            qh[kk][2] = *(const u32*)(qh_g + b0 + 8);
            qh[kk][3] = *(const u32*)(qh_g + b1 + 8);
            ql[kk][0] = *(const u32*)(ql_g + b0);
            ql[kk][1] = *(const u32*)(ql_g + b1);
            ql[kk][2] = *(const u32*)(ql_g + b0 + 8);
            ql[kk][3] = *(const u32*)(ql_g + b1 + 8);
        }

        float o[8][4];
#pragma unroll
        for (int nt = 0; nt < 8; nt++)
#pragma unroll
            for (int q = 0; q < 4; q++) o[nt][q] = 0.f;
        float m0 = -1e30f, m1 = -1e30f, l0 = 0.f, l1 = 0.f;

        const int n_t = (qt >= gp) ? ((qt - gp) / 3) + 1 : 0;
        if (n_t > 0) cp_tile(gbase, gp * 64, ltid, kh_g, kl_g, vh_g);

        for (int i = 0; i < n_t; i++) {
            const int kt = gp + 3 * i;
            const int t0 = kt * 64;
            if (i + 1 < n_t) {
                cp_tile(gbase + (u32)((i + 1) & 1) * BUF_WORDS * 4,
                        (gp + 3 * (i + 1)) * 64, ltid, kh_g, kl_g, vh_g);
                asm volatile("cp.async.wait_group 1;" ::: "memory");
            } else {
                asm volatile("cp.async.wait_group 0;" ::: "memory");
            }
            barg(1 + gp);

            const u32 bufb = gbase + (u32)(i & 1) * BUF_WORDS * 4;

            // ---- GEMM1: S = Q @ K^T (split-bf16 3-product) ----
            float s[8][4];
#pragma unroll
            for (int nt = 0; nt < 8; nt++)
#pragma unroll
                for (int q = 0; q < 4; q++) s[nt][q] = 0.f;
#pragma unroll
            for (int nt = 0; nt < 8; nt++) {
                const u32 bb0 = bufb + (u32)((nt * 8 + brow) * KTW + bsel * 4) * 4;
                u32 bh[4], bl[4];
                ldm_x4(bh, bb0);
                ldm_x4(bl, bb0 + PLANE * 4);
                mma16816(s[nt], qh[0], bh + 0);
                mma16816(s[nt], ql[0], bh + 0);
                mma16816(s[nt], qh[0], bl + 0);
                mma16816(s[nt], qh[1], bh + 2);
                mma16816(s[nt], ql[1], bh + 2);
                mma16816(s[nt], qh[1], bl + 2);
                ldm_x4(bh, bb0 + 64);
                ldm_x4(bl, bb0 + PLANE * 4 + 64);
                mma16816(s[nt], qh[2], bh + 0);
                mma16816(s[nt], ql[2], bh + 0);
                mma16816(s[nt], qh[2], bl + 0);
                mma16816(s[nt], qh[3], bh + 2);
                mma16816(s[nt], ql[3], bh + 2);
                mma16816(s[nt], qh[3], bl + 2);
            }

            if (kt == qt) {
                const int rg = qrow0 + r0;
#pragma unroll
                for (int nt = 0; nt < 8; nt++) {
                    const int col = t0 + nt * 8 + 2 * t;
                    if (col     > rg)     s[nt][0] = -1e30f;
                    if (col + 1 > rg)     s[nt][1] = -1e30f;
                    if (col     > rg + 8) s[nt][2] = -1e30f;
                    if (col + 1 > rg + 8) s[nt][3] = -1e30f;
                }
            }

            // ---- streaming softmax ----
            float mx0 = -1e30f, mx1 = -1e30f;
#pragma unroll
            for (int nt = 0; nt < 8; nt++) {
                mx0 = fmaxf(mx0, fmaxf(s[nt][0], s[nt][1]));
                mx1 = fmaxf(mx1, fmaxf(s[nt][2], s[nt][3]));
            }
            mx0 = fmaxf(mx0, __shfl_xor_sync(0xffffffffu, mx0, 1));
            mx0 = fmaxf(mx0, __shfl_xor_sync(0xffffffffu, mx0, 2));
            mx1 = fmaxf(mx1, __shfl_xor_sync(0xffffffffu, mx1, 1));
            mx1 = fmaxf(mx1, __shfl_xor_sync(0xffffffffu, mx1, 2));
            const float mn0 = fmaxf(m0, mx0), mn1 = fmaxf(m1, mx1);
            const float c0r = __expf(m0 - mn0), c1r = __expf(m1 - mn1);
            m0 = mn0; m1 = mn1;

            float s0 = 0.f, s1 = 0.f;
            u32 ph[4][4];
#pragma unroll
            for (int q2 = 0; q2 < 4; q2++) {
                float p00 = __expf(s[2*q2][0]   - mn0), p01 = __expf(s[2*q2][1]   - mn0);
                float p02 = __expf(s[2*q2][2]   - mn1), p03 = __expf(s[2*q2][3]   - mn1);
                float p10 = __expf(s[2*q2+1][0] - mn0), p11 = __expf(s[2*q2+1][1] - mn0);
                float p12 = __expf(s[2*q2+1][2] - mn1), p13 = __expf(s[2*q2+1][3] - mn1);
                s0 += (p00 + p01) + (p10 + p11);
                s1 += (p02 + p03) + (p12 + p13);
                ph[q2][0] = h2pk(p00, p01);
                ph[q2][1] = h2pk(p02, p03);
                ph[q2][2] = h2pk(p10, p11);
                ph[q2][3] = h2pk(p12, p13);
            }
            s0 += __shfl_xor_sync(0xffffffffu, s0, 1);
            s0 += __shfl_xor_sync(0xffffffffu, s0, 2);
            s1 += __shfl_xor_sync(0xffffffffu, s1, 1);
            s1 += __shfl_xor_sync(0xffffffffu, s1, 2);
            l0 = l0 * c0r + s0;
            l1 = l1 * c1r + s1;

#pragma unroll
            for (int nt = 0; nt < 8; nt++) {
                o[nt][0] *= c0r; o[nt][1] *= c0r;
                o[nt][2] *= c1r; o[nt][3] *= c1r;
            }

            // ---- GEMM2: O += P @ V (single-product fp16) ----
#pragma unroll
            for (int nt = 0; nt < 8; nt++) {
                const u32 vb0 = bufb + 2 * PLANE * 4
                              + (u32)((nt * 8 + brow) * KTW + bsel * 4) * 4;
                u32 bh[4];
                ldm_x4(bh, vb0);
                mma16816h(o[nt], ph[0], bh + 0);
                mma16816h(o[nt], ph[1], bh + 2);
                ldm_x4(bh, vb0 + 64);
                mma16816h(o[nt], ph[2], bh + 0);
                mma16816h(o[nt], ph[3], bh + 2);
            }
            barg(1 + gp);
        }

        // ---- 3-way merge (staging reuses group-0 buffers) ----
        __syncthreads();
        if (gp >= 1) {
            const int gi = gp - 1;
            float* mog = mo + gi * 64 * MO_STR;
            const int ra = r0, rb = r0 + 8;
#pragma unroll
            for (int nt = 0; nt < 8; nt++) {
                const int cc = nt * 8 + 2 * t;
                mog[ra * MO_STR + cc]     = o[nt][0];
                mog[ra * MO_STR + cc + 1] = o[nt][1];
                mog[rb * MO_STR + cc]     = o[nt][2];
                mog[rb * MO_STR + cc + 1] = o[nt][3];
            }
            if (t == 0) {
                mmv[gi * 64 + ra] = m0; mlv[gi * 64 + ra] = l0;
                mmv[gi * 64 + rb] = m1; mlv[gi * 64 + rb] = l1;
            }
        }
        __syncthreads();
        if (gp == 0) {
            const int ra = r0, rb = r0 + 8;
            const float m1a = mmv[ra],      l1a = mlv[ra];
            const float m2a = mmv[64 + ra], l2a = mlv[64 + ra];
            const float m1b = mmv[rb],      l1b = mlv[rb];
            const float m2b = mmv[64 + rb], l2b = mlv[64 + rb];
            const float msA = fmaxf(m0, fmaxf(m1a, m2a));
            const float msB = fmaxf(m1, fmaxf(m1b, m2b));
            const float f0A = __expf(m0 - msA), f1A = __expf(m1a - msA), f2A = __expf(m2a - msA);
            const float f0B = __expf(m1 - msB), f1B = __expf(m1b - msB), f2B = __expf(m2b - msB);
            const float invA = 1.f / (l0 * f0A + l1a * f1A + l2a * f2A);
            const float invB = 1.f / (l1 * f0B + l1b * f1B + l2b * f2B);
            const float* mo1 = mo;
            const float* mo2 = mo + 64 * MO_STR;
            float* orow0 = out + ((size_t)bb * TSEQ + qrow0 + ra) * HD;
            float* orow1 = out + ((size_t)bb * TSEQ + qrow0 + rb) * HD;
#pragma unroll
            for (int nt = 0; nt < 8; nt++) {
                const int cc = nt * 8 + 2 * t;
                float2 oa, ob;
                oa.x = (o[nt][0] * f0A + mo1[ra * MO_STR + cc]     * f1A
                                       + mo2[ra * MO_STR + cc]     * f2A) * invA;
                oa.y = (o[nt][1] * f0A + mo1[ra * MO_STR + cc + 1] * f1A
                                       + mo2[ra * MO_STR + cc + 1] * f2A) * invA;
                ob.x = (o[nt][2] * f0B + mo1[rb * MO_STR + cc]     * f1B
                                       + mo2[rb * MO_STR + cc]     * f2B) * invB;
                ob.y = (o[nt][3] * f0B + mo1[rb * MO_STR + cc + 1] * f1B
                                       + mo2[rb * MO_STR + cc + 1] * f2B) * invB;
                *reinterpret_cast<float2*>(orow0 + cc) = oa;
                *reinterpret_cast<float2*>(orow1 + cc) = ob;
            }
        }
        __syncthreads();
    }
}

// ---------------------------------------------------------------------------
extern "C" void kernel_launch(void* const* d_in, const int* in_sizes, int n_in,
                              void* d_out, int out_size)
{
    const float* x = (const float*)d_in[0];
    const float* W = (const float*)d_in[1];
    const float* b = (const float*)d_in[2];
    float* out = (float*)d_out;

    (void)in_sizes; (void)n_in; (void)out_size;

    static int attr_set = 0;
    if (!attr_set) {
        cudaFuncSetAttribute(attn_hmma_kernel,
                             cudaFuncAttributeMaxDynamicSharedMemorySize, ATTN_SMEM);
        cudaFuncSetAttribute(qkv_mma_kernel,
                             cudaFuncAttributeMaxDynamicSharedMemorySize, QKV_SMEM_BYTES);
        attr_set = 1;
    }

    wprep_kernel<<<(192 * CDIM + 255) / 256, 256>>>(W);
    qkv_mma_kernel<<<128, 384, QKV_SMEM_BYTES>>>(x, b);

    dim3 g2(16, BSZ);
    attn_hmma_kernel<<<g2, 384, ATTN_SMEM>>>(out);
}